// round 8
// baseline (speedup 1.0000x reference)
#include <cuda_runtime.h>
#include <cuda_fp16.h>

// VNL loss, fp16-packed gather + direct-L2 histogram trimmed mean.
// k_pack:    transpose (b,pixel) fp32 depth maps into d_pack[pixel][16 halves]
//            = {gt[0..7], pr[0..7]} (32B/pixel). Thread = (map, batch-half,
//            4-pixel quad): 1200 blocks, 4 LDG.128 + 4 STG.64 per thread.
// k_compute: one thread per group g; 6 LDG.128 fetch all 8 batches (fp16) of
//            3 pixels into registers; math in fp32. Per masked item ONE 64-bit
//            global atomicAdd (no return -> REDG) of ((round(L*128)<<22)|1)
//            into a 2048-bin histogram. No shared memory at all.
// k_resolve: one 1024-thread block; 2 bins/thread, block scan, rank-owner
//            resolves the quartile bin by bin-mean, re-zeros the histogram
//            (device globals are zero at module load -> replay invariant).

#define Wd 640
#define Hd 480
#define Bn 8
#define Gn 368640            // int(8*480*640*0.15)
#define NPIX (Hd * Wd)       // 307200
#define NQ (NPIX / 4)        // 76800 pixel quads
#define NB 2048
#define LMAXF 3.47f          // L <= 2*sqrt(3) ~ 3.4641
#define BIN_SCALE ((float)NB / LMAXF)
#define FIXSCALE 128.0f      // per-item quantization, unbiased rn
#define INV_FIXSCALE (1.0 / 128.0)
#define CNT_MASK 0x3FFFFFull // low 22 bits of global word = count (max 2.9M)

__device__ unsigned long long d_hist64[NB];   // zero-init at module load
__device__ __half d_pack[NPIX * 16];          // [pixel][gt0..7, pr0..7] halves

__global__ void __launch_bounds__(256) k_pack(
    const float* __restrict__ gt, const float* __restrict__ pr)
{
    const int t = blockIdx.x * blockDim.x + threadIdx.x;   // < 4*NQ
    const int q = t % NQ;
    const int r = t / NQ;          // 0..3
    const int map = r >> 1;        // 0 = gt, 1 = pr
    const int bh  = r & 1;         // batch half: batches [bh*4, bh*4+4)
    const int p = q * 4;           // base pixel
    const float* src = (map ? pr : gt) + bh * 4 * NPIX;

    float4 v[4];
    #pragma unroll
    for (int b = 0; b < 4; b++) v[b] = *(const float4*)(src + b * NPIX + p);

    #pragma unroll
    for (int i = 0; i < 4; i++) {
        const float* vf = (const float*)v;   // v[b] component i = vf[4*b+i]
        __half h[4];
        #pragma unroll
        for (int b = 0; b < 4; b++) h[b] = __float2half(vf[4 * b + i]);
        *(uint2*)(d_pack + (size_t)(p + i) * 16 + map * 8 + bh * 4) = *(const uint2*)h;
    }
}

__global__ void __launch_bounds__(256) k_compute(
    const int* __restrict__ p1x, const int* __restrict__ p1y,
    const int* __restrict__ p2x, const int* __restrict__ p2y,
    const int* __restrict__ p3x, const int* __restrict__ p3y)
{
    const int g = blockIdx.x * blockDim.x + threadIdx.x;   // grid covers Gn exactly

    const int x1 = p1x[g], y1 = p1y[g];
    const int x2 = p2x[g], y2 = p2y[g];
    const int x3 = p3x[g], y3 = p3y[g];

    const float ax1 = ((float)x1 - 320.0f) * (1.0f / 519.0f);
    const float ay1 = ((float)y1 - 240.0f) * (1.0f / 519.0f);
    const float ax2 = ((float)x2 - 320.0f) * (1.0f / 519.0f);
    const float ay2 = ((float)y2 - 240.0f) * (1.0f / 519.0f);
    const float ax3 = ((float)x3 - 320.0f) * (1.0f / 519.0f);
    const float ay3 = ((float)y3 - 240.0f) * (1.0f / 519.0f);

    const uint4* s1 = (const uint4*)(d_pack + (size_t)(y1 * Wd + x1) * 16);
    const uint4* s2 = (const uint4*)(d_pack + (size_t)(y2 * Wd + x2) * 16);
    const uint4* s3 = (const uint4*)(d_pack + (size_t)(y3 * Wd + x3) * 16);

    // 6 independent 16B loads -> all 8 batches resident; convert to fp32 regs
    float G1[8], Q1[8], G2[8], Q2[8], G3[8], Q3[8];
    {
        uint4 a;
        __half h[8];
        a = s1[0]; *(uint4*)h = a;
        #pragma unroll
        for (int b = 0; b < 8; b++) G1[b] = __half2float(h[b]);
        a = s1[1]; *(uint4*)h = a;
        #pragma unroll
        for (int b = 0; b < 8; b++) Q1[b] = __half2float(h[b]);
        a = s2[0]; *(uint4*)h = a;
        #pragma unroll
        for (int b = 0; b < 8; b++) G2[b] = __half2float(h[b]);
        a = s2[1]; *(uint4*)h = a;
        #pragma unroll
        for (int b = 0; b < 8; b++) Q2[b] = __half2float(h[b]);
        a = s3[0]; *(uint4*)h = a;
        #pragma unroll
        for (int b = 0; b < 8; b++) G3[b] = __half2float(h[b]);
        a = s3[1]; *(uint4*)h = a;
        #pragma unroll
        for (int b = 0; b < 8; b++) Q3[b] = __half2float(h[b]);
    }

    #pragma unroll
    for (int b = 0; b < Bn; b++) {
        const float gd1 = G1[b], gd2 = G2[b], gd3 = G3[b];
        const float qd1 = Q1[b], qd2 = Q2[b], qd3 = Q3[b];

        // ---- GT points & diffs ----
        const float g1x = ax1 * fabsf(gd1), g1y = ay1 * fabsf(gd1), g1z = gd1;
        const float g2x = ax2 * fabsf(gd2), g2y = ay2 * fabsf(gd2), g2z = gd2;
        const float g3x = ax3 * fabsf(gd3), g3y = ay3 * fabsf(gd3), g3z = gd3;

        const float d12x = g2x - g1x, d12y = g2y - g1y, d12z = g2z - g1z;
        const float d13x = g3x - g1x, d13y = g3y - g1y, d13z = g3z - g1z;
        const float d23x = g3x - g2x, d23y = g3y - g2y, d23z = g3z - g2z;

        const float e11 = d12x*d12x + d12y*d12y + d12z*d12z;
        const float e22 = d13x*d13x + d13y*d13y + d13z*d13z;
        const float e33 = d23x*d23x + d23y*d23y + d23z*d23z;
        const float e12 = d12x*d13x + d12y*d13y + d12z*d13z;
        const float e13 = d12x*d23x + d12y*d23y + d12z*d23z;
        const float e23 = d13x*d23x + d13y*d23y + d13z*d23z;

        const float n1 = sqrtf(e11), n2 = sqrtf(e22), n3 = sqrtf(e33);
        const float DC = 0.867f, EPS = 1e-8f;
        // |e_ij| > DC*(n_i*n_j + 1e-8)  <=>  |cos_ij| > DC
        int cnt = (fabsf(e11) > DC * (n1 * n1 + EPS))
                + (fabsf(e22) > DC * (n2 * n2 + EPS))
                + (fabsf(e33) > DC * (n3 * n3 + EPS))
                + 2 * ((fabsf(e12) > DC * (n1 * n2 + EPS))
                     + (fabsf(e13) > DC * (n1 * n3 + EPS))
                     + (fabsf(e23) > DC * (n2 * n3 + EPS)));
        const bool mcos = cnt > 3;
        const bool mx = (fabsf(d12x) < 0.01f) || (fabsf(d13x) < 0.01f) || (fabsf(d23x) < 0.01f);
        const bool my = (fabsf(d12y) < 0.01f) || (fabsf(d13y) < 0.01f) || (fabsf(d23y) < 0.01f);
        const bool mz = (fabsf(d12z) < 0.01f) || (fabsf(d13z) < 0.01f) || (fabsf(d23z) < 0.01f);
        const bool mask = !((mx && my && mz) || mcos);

        // ---- Pred points (reference's zmask broadcast bug replicated:
        //      z of point c == 0  =>  coordinate c of ALL points := 1e-4) ----
        float q1x = ax1 * fabsf(qd1), q1y = ay1 * fabsf(qd1), q1z = qd1;
        float q2x = ax2 * fabsf(qd2), q2y = ay2 * fabsf(qd2), q2z = qd2;
        float q3x = ax3 * fabsf(qd3), q3y = ay3 * fabsf(qd3), q3z = qd3;
        if (qd1 == 0.0f) { q1x = 1e-4f; q2x = 1e-4f; q3x = 1e-4f; }
        if (qd2 == 0.0f) { q1y = 1e-4f; q2y = 1e-4f; q3y = 1e-4f; }
        if (qd3 == 0.0f) { q1z = 1e-4f; q2z = 1e-4f; q3z = 1e-4f; }

        const float t12x = q2x - q1x, t12y = q2y - q1y, t12z = q2z - q1z;
        const float t13x = q3x - q1x, t13y = q3y - q1y, t13z = q3z - q1z;

        // ---- normals + L1 diff of unit normals ----
        const float gnx = d12y * d13z - d12z * d13y;
        const float gny = d12z * d13x - d12x * d13z;
        const float gnz = d12x * d13y - d12y * d13x;
        const float tnx = t12y * t13z - t12z * t13y;
        const float tny = t12z * t13x - t12x * t13z;
        const float tnz = t12x * t13y - t12y * t13x;

        const float gq = gnx * gnx + gny * gny + gnz * gnz;
        const float tq = tnx * tnx + tny * tny + tnz * tnz;
        const float gi = (gq == 0.0f) ? 100.0f : rsqrtf(gq);   // norm==0 -> norm:=0.01
        const float ti = (tq == 0.0f) ? 100.0f : rsqrtf(tq);

        const float L = fabsf(gnx * gi - tnx * ti)
                      + fabsf(gny * gi - tny * ti)
                      + fabsf(gnz * gi - tnz * ti);

        if (mask) {
            int bin = (int)(L * BIN_SCALE);
            bin = bin < 0 ? 0 : (bin > NB - 1 ? NB - 1 : bin);
            // sum field [22:64): max 2.95M*444 = 1.3e9 << 2^42; count [0:22)
            const unsigned long long v =
                ((unsigned long long)__float2uint_rn(L * FIXSCALE) << 22) | 1ull;
            atomicAdd(&d_hist64[bin], v);   // no return use -> REDG at L2
        }
    }
}

// One 1024-thread block resolves the trimmed mean, then re-zeros the histogram.
__global__ void __launch_bounds__(1024) k_resolve(float* out) {
    const int tid  = threadIdx.x;          // 0..1023
    const int lane = tid & 31;
    const int wid  = tid >> 5;             // 0..31

    // each thread owns bins 2*tid, 2*tid+1 (loaded once, kept in registers)
    const unsigned long long v0 = d_hist64[2 * tid];
    const unsigned long long v1 = d_hist64[2 * tid + 1];
    const int c0 = (int)(v0 & CNT_MASK), c1 = (int)(v1 & CNT_MASK);
    const double s0 = (double)(v0 >> 22) * INV_FIXSCALE;
    const double s1 = (double)(v1 >> 22) * INV_FIXSCALE;
    const int    lc = c0 + c1;
    const double ls = s0 + s1;

    // warp inclusive scans
    int ic = lc;
    double is = ls;
    #pragma unroll
    for (int o = 1; o < 32; o <<= 1) {
        int    vi = __shfl_up_sync(0xFFFFFFFFu, ic, o);
        double vd = __shfl_up_sync(0xFFFFFFFFu, is, o);
        if (lane >= o) { ic += vi; is += vd; }
    }

    __shared__ int    wc[32];
    __shared__ double ws[32];
    if (lane == 31) { wc[wid] = ic; ws[wid] = is; }
    __syncthreads();

    // warp 0 scans the 32 warp totals
    if (wid == 0) {
        int    a = wc[lane];
        double d = ws[lane];
        #pragma unroll
        for (int o = 1; o < 32; o <<= 1) {
            int    vi = __shfl_up_sync(0xFFFFFFFFu, a, o);
            double vd = __shfl_up_sync(0xFFFFFFFFu, d, o);
            if (lane >= o) { a += vi; d += vd; }
        }
        wc[lane] = a; ws[lane] = d;
    }
    __syncthreads();

    const int    wofc = (wid == 0) ? 0 : wc[wid - 1];
    const double wofs = (wid == 0) ? 0.0 : ws[wid - 1];
    ic += wofc;                  // block-inclusive prefix for this thread
    is += wofs;

    const int    n     = wc[31];
    const double total = ws[31];
    const int    drop  = n >> 2;

    const int    ec = ic - lc;   // exclusive prefixes
    const double es = is - ls;

    if (drop == 0) {
        if (tid == 0) {
            int denom = n; if (denom < 1) denom = 1;
            out[0] = (float)(total / (double)denom);
        }
    } else if (drop > ec && drop <= ic) {
        // exactly one thread owns rank 'drop'; resolve within its 2 bins
        double ds = es;
        int cum = ec;
        if (cum + c0 >= drop) {
            const int r = drop - cum;
            if (c0 > 0) ds += (double)r * (s0 / (double)c0);
        } else {
            cum += c0;
            ds += s0;
            const int r = drop - cum;
            if (c1 > 0) ds += (double)r * (s1 / (double)c1);
        }
        int denom = n - drop; if (denom < 1) denom = 1;
        out[0] = (float)((total - ds) / (double)denom);
    }

    // re-zero for the next replay
    d_hist64[2 * tid] = 0ull;
    d_hist64[2 * tid + 1] = 0ull;
}

extern "C" void kernel_launch(void* const* d_in, const int* in_sizes, int n_in,
                              void* d_out, int out_size) {
    const float* gt  = (const float*)d_in[0];
    const float* pr  = (const float*)d_in[1];
    const int*   p1x = (const int*)d_in[2];
    const int*   p1y = (const int*)d_in[3];
    const int*   p2x = (const int*)d_in[4];
    const int*   p2y = (const int*)d_in[5];
    const int*   p3x = (const int*)d_in[6];
    const int*   p3y = (const int*)d_in[7];

    k_pack<<<4 * NQ / 256, 256>>>(gt, pr);
    k_compute<<<Gn / 256, 256>>>(p1x, p1y, p2x, p2y, p3x, p3y);
    k_resolve<<<1, 1024>>>((float*)d_out);
}

// round 9
// speedup vs baseline: 1.7258x; 1.7258x over previous
#include <cuda_runtime.h>
#include <cuda_fp16.h>

// VNL loss, fp16 two-plane packed gather + smem-histogram trimmed mean.
// k_pack:    transpose (b,pixel) fp32 maps into two fp16 planes:
//            plane0[pixel][8] = gt batches, plane1[pixel][8] = pr batches
//            (16B/pixel/plane). Thread = (map, pixel): 8 coalesced LDG.32 +
//            ONE dense STG.128 (warp writes 512B contiguous). 2400 blocks.
// k_compute: one thread per group g; 6 LDG.128 gathers (3 pixels x 2 planes)
//            fetch all 8 batches into registers; math in fp32. Per masked item
//            one 32-bit shared atomic ((round(L*128)<<12)|1) into a 2048-bin
//            histogram; block flushes nonzero bins with one 64-bit global atomic.
// k_resolve: one 1024-thread block; 2 bins/thread, block scan, rank-owner
//            resolves the quartile bin by bin-mean, re-zeros the histogram
//            (device globals are zero at module load -> replay invariant).

#define Wd 640
#define Hd 480
#define Bn 8
#define Gn 368640            // int(8*480*640*0.15)
#define NPIX (Hd * Wd)       // 307200
#define NB 2048
#define LMAXF 3.47f          // L <= 2*sqrt(3) ~ 3.4641
#define BIN_SCALE ((float)NB / LMAXF)
#define FIXSCALE 128.0f      // per-item quantization, unbiased rn
#define INV_FIXSCALE (1.0 / 128.0)
#define SH_CNT_MASK 0xFFFu   // low 12 bits of shared word = count (max 2048/block)
#define CNT_MASK 0x3FFFFFull // low 22 bits of global word = count (max 2.9M)

__device__ unsigned long long d_hist64[NB];   // zero-init at module load
__device__ __half d_pack[2 * NPIX * 8];       // [plane][pixel][batch0..7]

__global__ void __launch_bounds__(256) k_pack(
    const float* __restrict__ gt, const float* __restrict__ pr)
{
    const int t = blockIdx.x * blockDim.x + threadIdx.x;   // < 2*NPIX
    const int sel = (t >= NPIX) ? 1 : 0;                   // warp-uniform (NPIX%32==0)
    const int p = t - sel * NPIX;
    const float* src = sel ? pr : gt;

    __half h[8];
    #pragma unroll
    for (int b = 0; b < Bn; b++) h[b] = __float2half(src[b * NPIX + p]);
    *(uint4*)(d_pack + (size_t)t * 8) = *(const uint4*)h;
}

__global__ void __launch_bounds__(256) k_compute(
    const int* __restrict__ p1x, const int* __restrict__ p1y,
    const int* __restrict__ p2x, const int* __restrict__ p2y,
    const int* __restrict__ p3x, const int* __restrict__ p3y)
{
    __shared__ unsigned int sh[NB];
    for (int j = threadIdx.x; j < NB; j += blockDim.x) sh[j] = 0u;
    __syncthreads();

    const int g = blockIdx.x * blockDim.x + threadIdx.x;   // grid covers Gn exactly

    const int x1 = p1x[g], y1 = p1y[g];
    const int x2 = p2x[g], y2 = p2y[g];
    const int x3 = p3x[g], y3 = p3y[g];

    const float ax1 = ((float)x1 - 320.0f) * (1.0f / 519.0f);
    const float ay1 = ((float)y1 - 240.0f) * (1.0f / 519.0f);
    const float ax2 = ((float)x2 - 320.0f) * (1.0f / 519.0f);
    const float ay2 = ((float)y2 - 240.0f) * (1.0f / 519.0f);
    const float ax3 = ((float)x3 - 320.0f) * (1.0f / 519.0f);
    const float ay3 = ((float)y3 - 240.0f) * (1.0f / 519.0f);

    const int o1 = y1 * Wd + x1;
    const int o2 = y2 * Wd + x2;
    const int o3 = y3 * Wd + x3;

    // 6 independent 16B gathers -> all 8 batches resident; convert to fp32
    float G1[8], Q1[8], G2[8], Q2[8], G3[8], Q3[8];
    {
        uint4 a;
        __half h[8];
        a = *(const uint4*)(d_pack + (size_t)o1 * 8);
        *(uint4*)h = a;
        #pragma unroll
        for (int b = 0; b < 8; b++) G1[b] = __half2float(h[b]);
        a = *(const uint4*)(d_pack + (size_t)(NPIX + o1) * 8);
        *(uint4*)h = a;
        #pragma unroll
        for (int b = 0; b < 8; b++) Q1[b] = __half2float(h[b]);
        a = *(const uint4*)(d_pack + (size_t)o2 * 8);
        *(uint4*)h = a;
        #pragma unroll
        for (int b = 0; b < 8; b++) G2[b] = __half2float(h[b]);
        a = *(const uint4*)(d_pack + (size_t)(NPIX + o2) * 8);
        *(uint4*)h = a;
        #pragma unroll
        for (int b = 0; b < 8; b++) Q2[b] = __half2float(h[b]);
        a = *(const uint4*)(d_pack + (size_t)o3 * 8);
        *(uint4*)h = a;
        #pragma unroll
        for (int b = 0; b < 8; b++) G3[b] = __half2float(h[b]);
        a = *(const uint4*)(d_pack + (size_t)(NPIX + o3) * 8);
        *(uint4*)h = a;
        #pragma unroll
        for (int b = 0; b < 8; b++) Q3[b] = __half2float(h[b]);
    }

    #pragma unroll
    for (int b = 0; b < Bn; b++) {
        const float gd1 = G1[b], gd2 = G2[b], gd3 = G3[b];
        const float qd1 = Q1[b], qd2 = Q2[b], qd3 = Q3[b];

        // ---- GT points & diffs ----
        const float g1x = ax1 * fabsf(gd1), g1y = ay1 * fabsf(gd1), g1z = gd1;
        const float g2x = ax2 * fabsf(gd2), g2y = ay2 * fabsf(gd2), g2z = gd2;
        const float g3x = ax3 * fabsf(gd3), g3y = ay3 * fabsf(gd3), g3z = gd3;

        const float d12x = g2x - g1x, d12y = g2y - g1y, d12z = g2z - g1z;
        const float d13x = g3x - g1x, d13y = g3y - g1y, d13z = g3z - g1z;
        const float d23x = g3x - g2x, d23y = g3y - g2y, d23z = g3z - g2z;

        const float e11 = d12x*d12x + d12y*d12y + d12z*d12z;
        const float e22 = d13x*d13x + d13y*d13y + d13z*d13z;
        const float e33 = d23x*d23x + d23y*d23y + d23z*d23z;
        const float e12 = d12x*d13x + d12y*d13y + d12z*d13z;
        const float e13 = d12x*d23x + d12y*d23y + d12z*d23z;
        const float e23 = d13x*d23x + d13y*d23y + d13z*d23z;

        const float n1 = sqrtf(e11), n2 = sqrtf(e22), n3 = sqrtf(e33);
        const float DC = 0.867f, EPS = 1e-8f;
        // |e_ij| > DC*(n_i*n_j + 1e-8)  <=>  |cos_ij| > DC
        int cnt = (fabsf(e11) > DC * (n1 * n1 + EPS))
                + (fabsf(e22) > DC * (n2 * n2 + EPS))
                + (fabsf(e33) > DC * (n3 * n3 + EPS))
                + 2 * ((fabsf(e12) > DC * (n1 * n2 + EPS))
                     + (fabsf(e13) > DC * (n1 * n3 + EPS))
                     + (fabsf(e23) > DC * (n2 * n3 + EPS)));
        const bool mcos = cnt > 3;
        const bool mx = (fabsf(d12x) < 0.01f) || (fabsf(d13x) < 0.01f) || (fabsf(d23x) < 0.01f);
        const bool my = (fabsf(d12y) < 0.01f) || (fabsf(d13y) < 0.01f) || (fabsf(d23y) < 0.01f);
        const bool mz = (fabsf(d12z) < 0.01f) || (fabsf(d13z) < 0.01f) || (fabsf(d23z) < 0.01f);
        const bool mask = !((mx && my && mz) || mcos);

        // ---- Pred points (reference's zmask broadcast bug replicated:
        //      z of point c == 0  =>  coordinate c of ALL points := 1e-4) ----
        float q1x = ax1 * fabsf(qd1), q1y = ay1 * fabsf(qd1), q1z = qd1;
        float q2x = ax2 * fabsf(qd2), q2y = ay2 * fabsf(qd2), q2z = qd2;
        float q3x = ax3 * fabsf(qd3), q3y = ay3 * fabsf(qd3), q3z = qd3;
        if (qd1 == 0.0f) { q1x = 1e-4f; q2x = 1e-4f; q3x = 1e-4f; }
        if (qd2 == 0.0f) { q1y = 1e-4f; q2y = 1e-4f; q3y = 1e-4f; }
        if (qd3 == 0.0f) { q1z = 1e-4f; q2z = 1e-4f; q3z = 1e-4f; }

        const float t12x = q2x - q1x, t12y = q2y - q1y, t12z = q2z - q1z;
        const float t13x = q3x - q1x, t13y = q3y - q1y, t13z = q3z - q1z;

        // ---- normals + L1 diff of unit normals ----
        const float gnx = d12y * d13z - d12z * d13y;
        const float gny = d12z * d13x - d12x * d13z;
        const float gnz = d12x * d13y - d12y * d13x;
        const float tnx = t12y * t13z - t12z * t13y;
        const float tny = t12z * t13x - t12x * t13z;
        const float tnz = t12x * t13y - t12y * t13x;

        const float gq = gnx * gnx + gny * gny + gnz * gnz;
        const float tq = tnx * tnx + tny * tny + tnz * tnz;
        const float gi = (gq == 0.0f) ? 100.0f : rsqrtf(gq);   // norm==0 -> norm:=0.01
        const float ti = (tq == 0.0f) ? 100.0f : rsqrtf(tq);

        const float L = fabsf(gnx * gi - tnx * ti)
                      + fabsf(gny * gi - tny * ti)
                      + fabsf(gnz * gi - tnz * ti);

        if (mask) {
            int bin = (int)(L * BIN_SCALE);
            bin = bin < 0 ? 0 : (bin > NB - 1 ? NB - 1 : bin);
            // sum field [12:32) max 2048*444 = 909312 < 2^20; count [0:12) max 2048
            const unsigned int v = (__float2uint_rn(L * FIXSCALE) << 12) | 1u;
            atomicAdd(&sh[bin], v);
        }
    }

    __syncthreads();
    for (int j = threadIdx.x; j < NB; j += blockDim.x) {
        const unsigned int v = sh[j];
        if (v) {
            const unsigned long long gv =
                ((unsigned long long)(v >> 12) << 22) | (unsigned long long)(v & SH_CNT_MASK);
            atomicAdd(&d_hist64[j], gv);
        }
    }
}

// One 1024-thread block resolves the trimmed mean, then re-zeros the histogram.
__global__ void __launch_bounds__(1024) k_resolve(float* out) {
    const int tid  = threadIdx.x;          // 0..1023
    const int lane = tid & 31;
    const int wid  = tid >> 5;             // 0..31

    // each thread owns bins 2*tid, 2*tid+1 (loaded once, kept in registers)
    const unsigned long long v0 = d_hist64[2 * tid];
    const unsigned long long v1 = d_hist64[2 * tid + 1];
    const int c0 = (int)(v0 & CNT_MASK), c1 = (int)(v1 & CNT_MASK);
    const double s0 = (double)(v0 >> 22) * INV_FIXSCALE;
    const double s1 = (double)(v1 >> 22) * INV_FIXSCALE;
    const int    lc = c0 + c1;
    const double ls = s0 + s1;

    // warp inclusive scans
    int ic = lc;
    double is = ls;
    #pragma unroll
    for (int o = 1; o < 32; o <<= 1) {
        int    vi = __shfl_up_sync(0xFFFFFFFFu, ic, o);
        double vd = __shfl_up_sync(0xFFFFFFFFu, is, o);
        if (lane >= o) { ic += vi; is += vd; }
    }

    __shared__ int    wc[32];
    __shared__ double ws[32];
    if (lane == 31) { wc[wid] = ic; ws[wid] = is; }
    __syncthreads();

    // warp 0 scans the 32 warp totals
    if (wid == 0) {
        int    a = wc[lane];
        double d = ws[lane];
        #pragma unroll
        for (int o = 1; o < 32; o <<= 1) {
            int    vi = __shfl_up_sync(0xFFFFFFFFu, a, o);
            double vd = __shfl_up_sync(0xFFFFFFFFu, d, o);
            if (lane >= o) { a += vi; d += vd; }
        }
        wc[lane] = a; ws[lane] = d;
    }
    __syncthreads();

    const int    wofc = (wid == 0) ? 0 : wc[wid - 1];
    const double wofs = (wid == 0) ? 0.0 : ws[wid - 1];
    ic += wofc;                  // block-inclusive prefix for this thread
    is += wofs;

    const int    n     = wc[31];
    const double total = ws[31];
    const int    drop  = n >> 2;

    const int    ec = ic - lc;   // exclusive prefixes
    const double es = is - ls;

    if (drop == 0) {
        if (tid == 0) {
            int denom = n; if (denom < 1) denom = 1;
            out[0] = (float)(total / (double)denom);
        }
    } else if (drop > ec && drop <= ic) {
        // exactly one thread owns rank 'drop'; resolve within its 2 bins
        double ds = es;
        int cum = ec;
        if (cum + c0 >= drop) {
            const int r = drop - cum;
            if (c0 > 0) ds += (double)r * (s0 / (double)c0);
        } else {
            cum += c0;
            ds += s0;
            const int r = drop - cum;
            if (c1 > 0) ds += (double)r * (s1 / (double)c1);
        }
        int denom = n - drop; if (denom < 1) denom = 1;
        out[0] = (float)((total - ds) / (double)denom);
    }

    // re-zero for the next replay
    d_hist64[2 * tid] = 0ull;
    d_hist64[2 * tid + 1] = 0ull;
}

extern "C" void kernel_launch(void* const* d_in, const int* in_sizes, int n_in,
                              void* d_out, int out_size) {
    const float* gt  = (const float*)d_in[0];
    const float* pr  = (const float*)d_in[1];
    const int*   p1x = (const int*)d_in[2];
    const int*   p1y = (const int*)d_in[3];
    const int*   p2x = (const int*)d_in[4];
    const int*   p2y = (const int*)d_in[5];
    const int*   p3x = (const int*)d_in[6];
    const int*   p3y = (const int*)d_in[7];

    k_pack<<<2 * NPIX / 256, 256>>>(gt, pr);
    k_compute<<<Gn / 256, 256>>>(p1x, p1y, p2x, p2y, p3x, p3y);
    k_resolve<<<1, 1024>>>((float*)d_out);
}